// round 1
// baseline (speedup 1.0000x reference)
#include <cuda_runtime.h>
#include <math.h>

#define T 4096
#define C 256
#define B 4

// Scratch (allocation-free rule: __device__ globals)
__device__ float g_normed[B * C * T];        // 16 MB
__device__ float g_qkv[B * 3 * C * T];       // 48 MB
__device__ float g_h[B * C * T];             // 16 MB

// ---------------------------------------------------------------------------
// GroupNorm: 16 groups of 16 channels, stats over (16ch x 4096) = 65536 elems
// One block per (batch, group).
// ---------------------------------------------------------------------------
__global__ void groupnorm_kernel(const float* __restrict__ x,
                                 const float* __restrict__ w,
                                 const float* __restrict__ bias,
                                 float* __restrict__ out)
{
    const int CH = 16;             // channels per group
    const int N  = CH * T;         // 65536
    int bg = blockIdx.x;
    int b = bg >> 4, g = bg & 15;
    const float* xb = x   + ((size_t)b * C + g * CH) * T;
    float*       ob = out + ((size_t)b * C + g * CH) * T;

    float s = 0.f, ss = 0.f;
    for (int i = threadIdx.x; i < N; i += 256) {
        float v = xb[i];
        s += v; ss += v * v;
    }
    __shared__ float rs[256], rss[256];
    rs[threadIdx.x] = s; rss[threadIdx.x] = ss;
    __syncthreads();
    for (int off = 128; off > 0; off >>= 1) {
        if (threadIdx.x < off) {
            rs[threadIdx.x]  += rs[threadIdx.x + off];
            rss[threadIdx.x] += rss[threadIdx.x + off];
        }
        __syncthreads();
    }
    float mean = rs[0] * (1.f / N);
    float var  = rss[0] * (1.f / N) - mean * mean;
    float inv  = rsqrtf(var + 1e-5f);

    for (int i = threadIdx.x; i < N; i += 256) {
        int ch = g * CH + (i >> 12);        // 4096 = 2^12
        ob[i] = (xb[i] - mean) * inv * w[ch] + bias[ch];
    }
}

// ---------------------------------------------------------------------------
// Generic tiled GEMM: out[b][o][t] = sum_c W[o][c] * X[b][c][t] + bias[o]
//                     (+ res[b][o][t] if res != nullptr)
// Tile: 64(M) x 64(N), K-step 16. 256 threads, 4x4 register microtiles.
// ---------------------------------------------------------------------------
__global__ void gemm_kernel(const float* __restrict__ W,
                            const float* __restrict__ X,
                            const float* __restrict__ bias,
                            const float* __restrict__ res,
                            float* __restrict__ out,
                            int K, size_t strideX, size_t strideO, size_t strideR)
{
    __shared__ __align__(16) float Wt[16][68];   // [k][o_local]
    __shared__ __align__(16) float Xt[16][68];   // [k][t_local]

    int t0 = blockIdx.x * 64;
    int o0 = blockIdx.y * 64;
    int b  = blockIdx.z;
    const float* Xb = X + (size_t)b * strideX;
    float*       Ob = out + (size_t)b * strideO;

    int tid = threadIdx.x;
    int ty = tid >> 4, tx = tid & 15;

    float acc[4][4] = {};

    for (int kk = 0; kk < K; kk += 16) {
        for (int idx = tid; idx < 64 * 16; idx += 256) {
            int ol = idx >> 4, c = idx & 15;
            Wt[c][ol] = W[(size_t)(o0 + ol) * K + kk + c];
        }
        for (int idx = tid; idx < 16 * 64; idx += 256) {
            int kl = idx >> 6, tl = idx & 63;
            Xt[kl][tl] = Xb[(size_t)(kk + kl) * T + t0 + tl];
        }
        __syncthreads();

        #pragma unroll
        for (int k = 0; k < 16; k++) {
            float4 a4 = *(const float4*)&Wt[k][ty * 4];
            float4 b4 = *(const float4*)&Xt[k][tx * 4];
            float aa[4] = {a4.x, a4.y, a4.z, a4.w};
            float bb[4] = {b4.x, b4.y, b4.z, b4.w};
            #pragma unroll
            for (int i = 0; i < 4; i++)
                #pragma unroll
                for (int j = 0; j < 4; j++)
                    acc[i][j] += aa[i] * bb[j];
        }
        __syncthreads();
    }

    #pragma unroll
    for (int i = 0; i < 4; i++) {
        int o = o0 + ty * 4 + i;
        float bv = bias[o];
        #pragma unroll
        for (int j = 0; j < 4; j++) {
            int t = t0 + tx * 4 + j;
            float v = acc[i][j] + bv;
            if (res) v += res[(size_t)b * strideR + (size_t)o * T + t];
            Ob[(size_t)o * T + t] = v;
        }
    }
}

// ---------------------------------------------------------------------------
// Flash attention, fp32. One block = 64 queries of one (batch, head).
// q/k/v each [64ch x 4096] slices of g_qkv. Online softmax over 64-key tiles.
// ---------------------------------------------------------------------------
__global__ void attn_kernel(const float* __restrict__ qkv,
                            float* __restrict__ hout)
{
    extern __shared__ __align__(16) float sm[];
    float (*Qs)[68] = (float(*)[68])(sm);
    float (*Ks)[68] = (float(*)[68])(sm + 1 * 64 * 68);
    float (*Vs)[68] = (float(*)[68])(sm + 2 * 64 * 68);
    float (*Ss)[68] = (float(*)[68])(sm + 3 * 64 * 68);
    float* m_s = sm + 4 * 64 * 68;
    float* l_s = m_s + 64;
    float* rsc = l_s + 64;

    int t0 = blockIdx.x * 64;
    int bh = blockIdx.y;
    int b = bh >> 2, hd = bh & 3;
    const float* qp = qkv + ((size_t)b * 768 + (size_t)hd * 192) * T;
    const float* kp = qp + (size_t)64 * T;
    const float* vp = qp + (size_t)128 * T;

    int tid = threadIdx.x;
    int ty = tid >> 4, tx = tid & 15;

    // Load Q tile [64ch][64t]
    for (int idx = tid; idx < 64 * 64; idx += 256) {
        int ch = idx >> 6, t = idx & 63;
        Qs[ch][t] = qp[(size_t)ch * T + t0 + t];
    }
    if (tid < 64) { m_s[tid] = -1e30f; l_s[tid] = 0.f; }
    __syncthreads();

    float acc[4][4] = {};   // acc[ch_local][q_local]

    for (int s0 = 0; s0 < T; s0 += 64) {
        // Load K, V tiles
        for (int idx = tid; idx < 64 * 64; idx += 256) {
            int ch = idx >> 6, s = idx & 63;
            Ks[ch][s] = kp[(size_t)ch * T + s0 + s];
            Vs[ch][s] = vp[(size_t)ch * T + s0 + s];
        }
        __syncthreads();

        // Scores: S[tq][s] = (1/8) * sum_c Q[c][tq] K[c][s]
        float sreg[4][4] = {};
        #pragma unroll 16
        for (int c = 0; c < 64; c++) {
            float4 q4 = *(const float4*)&Qs[c][ty * 4];
            float4 k4 = *(const float4*)&Ks[c][tx * 4];
            float qa[4] = {q4.x, q4.y, q4.z, q4.w};
            float ka[4] = {k4.x, k4.y, k4.z, k4.w};
            #pragma unroll
            for (int i = 0; i < 4; i++)
                #pragma unroll
                for (int j = 0; j < 4; j++)
                    sreg[i][j] += qa[i] * ka[j];
        }
        #pragma unroll
        for (int i = 0; i < 4; i++) {
            float4 sv = make_float4(sreg[i][0] * 0.125f, sreg[i][1] * 0.125f,
                                    sreg[i][2] * 0.125f, sreg[i][3] * 0.125f);
            *(float4*)&Ss[ty * 4 + i][tx * 4] = sv;
        }
        __syncthreads();

        // Online softmax stats per query row (threads 0..63)
        if (tid < 64) {
            float mold = m_s[tid];
            float mx = mold;
            #pragma unroll 8
            for (int s = 0; s < 64; s++) mx = fmaxf(mx, Ss[tid][s]);
            float r = __expf(mold - mx);
            float sum = 0.f;
            #pragma unroll 8
            for (int s = 0; s < 64; s++) {
                float e = __expf(Ss[tid][s] - mx);
                Ss[tid][s] = e;
                sum += e;
            }
            m_s[tid] = mx;
            l_s[tid] = l_s[tid] * r + sum;
            rsc[tid] = r;
        }
        __syncthreads();

        // Rescale accumulators, then PV: acc[c][t] += sum_s P[t][s] V[c][s]
        float rj[4];
        #pragma unroll
        for (int j = 0; j < 4; j++) rj[j] = rsc[tx * 4 + j];
        #pragma unroll
        for (int i = 0; i < 4; i++)
            #pragma unroll
            for (int j = 0; j < 4; j++)
                acc[i][j] *= rj[j];

        #pragma unroll 4
        for (int s = 0; s < 64; s += 4) {
            float4 vv[4], pp[4];
            #pragma unroll
            for (int i = 0; i < 4; i++) vv[i] = *(const float4*)&Vs[ty * 4 + i][s];
            #pragma unroll
            for (int j = 0; j < 4; j++) pp[j] = *(const float4*)&Ss[tx * 4 + j][s];
            #pragma unroll
            for (int i = 0; i < 4; i++)
                #pragma unroll
                for (int j = 0; j < 4; j++)
                    acc[i][j] += vv[i].x * pp[j].x + vv[i].y * pp[j].y +
                                 vv[i].z * pp[j].z + vv[i].w * pp[j].w;
        }
        __syncthreads();
    }

    // Epilogue: divide by l, write h[b][hd*64 + c][t]
    #pragma unroll
    for (int j = 0; j < 4; j++) {
        float inv = 1.f / l_s[tx * 4 + j];
        int t = t0 + tx * 4 + j;
        #pragma unroll
        for (int i = 0; i < 4; i++) {
            int c = hd * 64 + ty * 4 + i;
            hout[((size_t)b * 256 + c) * T + t] = acc[i][j] * inv;
        }
    }
}

// ---------------------------------------------------------------------------
// Launch
// ---------------------------------------------------------------------------
extern "C" void kernel_launch(void* const* d_in, const int* in_sizes, int n_in,
                              void* d_out, int out_size)
{
    const float* x      = (const float*)d_in[0];
    const float* norm_w = (const float*)d_in[1];
    const float* norm_b = (const float*)d_in[2];
    const float* qkv_w  = (const float*)d_in[3];
    const float* qkv_b  = (const float*)d_in[4];
    const float* proj_w = (const float*)d_in[5];
    const float* proj_b = (const float*)d_in[6];
    float* out = (float*)d_out;

    float *normed_p, *qkv_p, *h_p;
    cudaGetSymbolAddress((void**)&normed_p, g_normed);
    cudaGetSymbolAddress((void**)&qkv_p,   g_qkv);
    cudaGetSymbolAddress((void**)&h_p,     g_h);

    // 1. GroupNorm
    groupnorm_kernel<<<B * 16, 256>>>(x, norm_w, norm_b, normed_p);

    // 2. QKV GEMM: [768,256] x [256,4096] per batch, + bias
    gemm_kernel<<<dim3(T / 64, 768 / 64, B), 256>>>(
        qkv_w, normed_p, qkv_b, nullptr, qkv_p,
        256, (size_t)C * T, (size_t)768 * T, 0);

    // 3. Flash attention: 16 (b,h) x 64 query tiles
    const int ATTN_SMEM = (4 * 64 * 68 + 3 * 64) * sizeof(float);  // 70400 B
    cudaFuncSetAttribute(attn_kernel, cudaFuncAttributeMaxDynamicSharedMemorySize,
                         ATTN_SMEM);
    attn_kernel<<<dim3(T / 64, 16), 256, ATTN_SMEM>>>(qkv_p, h_p);

    // 4. Proj GEMM + bias + residual -> d_out
    gemm_kernel<<<dim3(T / 64, 256 / 64, B), 256>>>(
        proj_w, h_p, proj_b, x, out,
        256, (size_t)C * T, (size_t)C * T, (size_t)C * T);
}

// round 2
// speedup vs baseline: 3.0092x; 3.0092x over previous
#include <cuda_runtime.h>
#include <math.h>

#define T 4096
#define C 256
#define B 4

// Scratch (allocation-free rule: __device__ globals)
__device__ float g_normed[B * C * T];
__device__ float g_qkv[B * 3 * C * T];
__device__ float g_h[B * C * T];

// ---------------------------------------------------------------------------
// tf32 helpers
// ---------------------------------------------------------------------------
__device__ __forceinline__ unsigned f2tf32(float f) {
    unsigned r;
    asm("cvt.rna.tf32.f32 %0, %1;" : "=r"(r) : "f"(f));
    return r;
}

__device__ __forceinline__ void mma_tf32(float* d, const unsigned* a,
                                         unsigned b0, unsigned b1) {
    asm volatile(
        "mma.sync.aligned.m16n8k8.row.col.f32.tf32.tf32.f32 "
        "{%0,%1,%2,%3}, {%4,%5,%6,%7}, {%8,%9}, {%0,%1,%2,%3};"
        : "+f"(d[0]), "+f"(d[1]), "+f"(d[2]), "+f"(d[3])
        : "r"(a[0]), "r"(a[1]), "r"(a[2]), "r"(a[3]), "r"(b0), "r"(b1));
}

// ---------------------------------------------------------------------------
// GroupNorm: 16 groups of 16 channels (unchanged from passing R1)
// ---------------------------------------------------------------------------
__global__ void groupnorm_kernel(const float* __restrict__ x,
                                 const float* __restrict__ w,
                                 const float* __restrict__ bias,
                                 float* __restrict__ out)
{
    const int CH = 16;
    const int N  = CH * T;
    int bg = blockIdx.x;
    int b = bg >> 4, g = bg & 15;
    const float* xb = x   + ((size_t)b * C + g * CH) * T;
    float*       ob = out + ((size_t)b * C + g * CH) * T;

    float s = 0.f, ss = 0.f;
    for (int i = threadIdx.x; i < N; i += 256) {
        float v = xb[i];
        s += v; ss += v * v;
    }
    __shared__ float rs[256], rss[256];
    rs[threadIdx.x] = s; rss[threadIdx.x] = ss;
    __syncthreads();
    for (int off = 128; off > 0; off >>= 1) {
        if (threadIdx.x < off) {
            rs[threadIdx.x]  += rs[threadIdx.x + off];
            rss[threadIdx.x] += rss[threadIdx.x + off];
        }
        __syncthreads();
    }
    float mean = rs[0] * (1.f / N);
    float var  = rss[0] * (1.f / N) - mean * mean;
    float inv  = rsqrtf(var + 1e-5f);

    for (int i = threadIdx.x; i < N; i += 256) {
        int ch = g * CH + (i >> 12);
        ob[i] = (xb[i] - mean) * inv * w[ch] + bias[ch];
    }
}

// ---------------------------------------------------------------------------
// Generic tiled GEMM (unchanged from passing R1)
// ---------------------------------------------------------------------------
__global__ void gemm_kernel(const float* __restrict__ W,
                            const float* __restrict__ X,
                            const float* __restrict__ bias,
                            const float* __restrict__ res,
                            float* __restrict__ out,
                            int K, size_t strideX, size_t strideO, size_t strideR)
{
    __shared__ __align__(16) float Wt[16][68];
    __shared__ __align__(16) float Xt[16][68];

    int t0 = blockIdx.x * 64;
    int o0 = blockIdx.y * 64;
    int b  = blockIdx.z;
    const float* Xb = X + (size_t)b * strideX;
    float*       Ob = out + (size_t)b * strideO;

    int tid = threadIdx.x;
    int ty = tid >> 4, tx = tid & 15;

    float acc[4][4] = {};

    for (int kk = 0; kk < K; kk += 16) {
        for (int idx = tid; idx < 64 * 16; idx += 256) {
            int ol = idx >> 4, c = idx & 15;
            Wt[c][ol] = W[(size_t)(o0 + ol) * K + kk + c];
        }
        for (int idx = tid; idx < 16 * 64; idx += 256) {
            int kl = idx >> 6, tl = idx & 63;
            Xt[kl][tl] = Xb[(size_t)(kk + kl) * T + t0 + tl];
        }
        __syncthreads();

        #pragma unroll
        for (int k = 0; k < 16; k++) {
            float4 a4 = *(const float4*)&Wt[k][ty * 4];
            float4 b4 = *(const float4*)&Xt[k][tx * 4];
            float aa[4] = {a4.x, a4.y, a4.z, a4.w};
            float bb[4] = {b4.x, b4.y, b4.z, b4.w};
            #pragma unroll
            for (int i = 0; i < 4; i++)
                #pragma unroll
                for (int j = 0; j < 4; j++)
                    acc[i][j] += aa[i] * bb[j];
        }
        __syncthreads();
    }

    #pragma unroll
    for (int i = 0; i < 4; i++) {
        int o = o0 + ty * 4 + i;
        float bv = bias[o];
        #pragma unroll
        for (int j = 0; j < 4; j++) {
            int t = t0 + tx * 4 + j;
            float v = acc[i][j] + bv;
            if (res) v += res[(size_t)b * strideR + (size_t)o * T + t];
            Ob[(size_t)o * T + t] = v;
        }
    }
}

// ---------------------------------------------------------------------------
// Flash attention with tf32 mma.sync (tensor pipe).
// Block: 128 queries (8 warps x 16 rows), key tiles of 64, d = 64.
// QK^T: S[t][s] = Q^T K  (A = Q^T from regs, B = K from smem [c][s])
// PV:   O[c][t] = V'[c][s] P'[s][t]  (A = V untransposed [c][s], B = P^T)
// Online softmax in registers (quad shuffles); P through smem for re-frag.
// ---------------------------------------------------------------------------
#define BM 128
#define PADK 68
#define PADP 68

__global__ void __launch_bounds__(256, 2)
attn_kernel(const float* __restrict__ qkv, float* __restrict__ hout)
{
    extern __shared__ unsigned smu[];
    unsigned* Ks = smu;                    // [64][PADK]  tf32 bits
    unsigned* Vs = Ks + 64 * PADK;         // [64][PADK]  tf32 bits
    unsigned* Ps = Vs + 64 * PADK;         // [BM][PADP]  tf32 bits
    float* rsc = (float*)(Ps + BM * PADP); // [BM] per-tile rescale
    float* l_s = rsc + BM;                 // [BM] final denominators

    int t0 = blockIdx.x * BM;
    int bh = blockIdx.y;
    int b = bh >> 2, hd = bh & 3;
    const float* qp = qkv + ((size_t)b * 768 + (size_t)hd * 192) * T;
    const float* kp = qp + (size_t)64 * T;
    const float* vp = qp + (size_t)128 * T;

    int tid = threadIdx.x;
    int w = tid >> 5;
    int lane = tid & 31;
    int qr = lane >> 2;   // groupID   (0..7)
    int ql = lane & 3;    // threadID_in_group (0..3)

    // ---- Q fragments in registers: warp w owns query rows [16w, 16w+16) ----
    // A layout m16n8k8.tf32: a0(r=qr,c=ql) a1(r=qr+8,c=ql) a2(r=qr,c=ql+4) a3(r=qr+8,c=ql+4)
    unsigned qf[8][4];
    {
        int tq = t0 + 16 * w + qr;
        #pragma unroll
        for (int k = 0; k < 8; k++) {
            int c = k * 8 + ql;
            qf[k][0] = f2tf32(qp[(size_t)c * T + tq] * 0.125f);
            qf[k][1] = f2tf32(qp[(size_t)c * T + tq + 8] * 0.125f);
            qf[k][2] = f2tf32(qp[(size_t)(c + 4) * T + tq] * 0.125f);
            qf[k][3] = f2tf32(qp[(size_t)(c + 4) * T + tq + 8] * 0.125f);
        }
    }

    // PV output partition: warp w -> c-tile mi (16 channels), 8 t-tiles (64 t)
    int mi = w & 3;
    int nb = (w >> 2) * 8;

    float o[8][4] = {};
    float m0 = -1e30f, m1 = -1e30f, l0 = 0.f, l1 = 0.f;

    for (int s0 = 0; s0 < T; s0 += 64) {
        __syncthreads();
        // ---- load K, V tiles (coalesced, tf32-convert at store) ----
        for (int idx = tid; idx < 4096; idx += 256) {
            int c = idx >> 6, s = idx & 63;
            Ks[c * PADK + s] = f2tf32(kp[(size_t)c * T + s0 + s]);
            Vs[c * PADK + s] = f2tf32(vp[(size_t)c * T + s0 + s]);
        }
        __syncthreads();

        // ---- S = Q^T K : warp owns rows 16w..16w+15, cols 0..63 ----
        float sf[8][4] = {};
        #pragma unroll
        for (int k = 0; k < 8; k++) {
            #pragma unroll
            for (int n = 0; n < 8; n++) {
                unsigned b0 = Ks[(k * 8 + ql) * PADK + n * 8 + qr];
                unsigned b1 = Ks[(k * 8 + ql + 4) * PADK + n * 8 + qr];
                mma_tf32(sf[n], qf[k], b0, b1);
            }
        }

        // ---- online softmax (rows r0 = 16w+qr, r1 = r0+8) ----
        float mx0 = -1e30f, mx1 = -1e30f;
        #pragma unroll
        for (int n = 0; n < 8; n++) {
            mx0 = fmaxf(mx0, fmaxf(sf[n][0], sf[n][1]));
            mx1 = fmaxf(mx1, fmaxf(sf[n][2], sf[n][3]));
        }
        mx0 = fmaxf(mx0, __shfl_xor_sync(0xffffffffu, mx0, 1));
        mx0 = fmaxf(mx0, __shfl_xor_sync(0xffffffffu, mx0, 2));
        mx1 = fmaxf(mx1, __shfl_xor_sync(0xffffffffu, mx1, 1));
        mx1 = fmaxf(mx1, __shfl_xor_sync(0xffffffffu, mx1, 2));

        float mn0 = fmaxf(m0, mx0), mn1 = fmaxf(m1, mx1);
        float r0 = __expf(m0 - mn0), r1 = __expf(m1 - mn1);
        m0 = mn0; m1 = mn1;

        float sum0 = 0.f, sum1 = 0.f;
        unsigned* prow0 = Ps + (16 * w + qr) * PADP;
        unsigned* prow1 = prow0 + 8 * PADP;
        #pragma unroll
        for (int n = 0; n < 8; n++) {
            float p00 = __expf(sf[n][0] - mn0);
            float p01 = __expf(sf[n][1] - mn0);
            float p10 = __expf(sf[n][2] - mn1);
            float p11 = __expf(sf[n][3] - mn1);
            sum0 += p00 + p01;
            sum1 += p10 + p11;
            int cbase = n * 8 + ql * 2;
            prow0[cbase]     = f2tf32(p00);
            prow0[cbase + 1] = f2tf32(p01);
            prow1[cbase]     = f2tf32(p10);
            prow1[cbase + 1] = f2tf32(p11);
        }
        sum0 += __shfl_xor_sync(0xffffffffu, sum0, 1);
        sum0 += __shfl_xor_sync(0xffffffffu, sum0, 2);
        sum1 += __shfl_xor_sync(0xffffffffu, sum1, 1);
        sum1 += __shfl_xor_sync(0xffffffffu, sum1, 2);
        l0 = l0 * r0 + sum0;
        l1 = l1 * r1 + sum1;
        if (ql == 0) {
            rsc[16 * w + qr]     = r0;
            rsc[16 * w + qr + 8] = r1;
        }
        __syncthreads();

        // ---- rescale accumulators by rsc[t] (t = column dim of O) ----
        #pragma unroll
        for (int j = 0; j < 8; j++) {
            float ra = rsc[(nb + j) * 8 + ql * 2];
            float rb = rsc[(nb + j) * 8 + ql * 2 + 1];
            o[j][0] *= ra; o[j][1] *= rb; o[j][2] *= ra; o[j][3] *= rb;
        }

        // ---- O[c][t] += V'[c][s] * P'[s][t] ----
        #pragma unroll
        for (int k = 0; k < 8; k++) {
            unsigned a[4];
            int crow = (mi * 16 + qr) * PADK;
            a[0] = Vs[crow + k * 8 + ql];
            a[1] = Vs[crow + 8 * PADK + k * 8 + ql];
            a[2] = Vs[crow + k * 8 + ql + 4];
            a[3] = Vs[crow + 8 * PADK + k * 8 + ql + 4];
            #pragma unroll
            for (int j = 0; j < 8; j++) {
                int trow = ((nb + j) * 8 + qr) * PADP;
                unsigned b0 = Ps[trow + k * 8 + ql];
                unsigned b1 = Ps[trow + k * 8 + ql + 4];
                mma_tf32(o[j], a, b0, b1);
            }
        }
    }

    // ---- epilogue: divide by l, write h[b][hd*64+c][t] ----
    if (ql == 0) {
        l_s[16 * w + qr]     = l0;
        l_s[16 * w + qr + 8] = l1;
    }
    __syncthreads();

    #pragma unroll
    for (int j = 0; j < 8; j++) {
        int tl = (nb + j) * 8 + ql * 2;
        float ia = 1.f / l_s[tl];
        float ib = 1.f / l_s[tl + 1];
        int t = t0 + tl;
        int c0g = hd * 64 + mi * 16 + qr;
        size_t base0 = ((size_t)b * 256 + c0g) * T + t;
        size_t base1 = ((size_t)b * 256 + c0g + 8) * T + t;
        hout[base0]     = o[j][0] * ia;
        hout[base0 + 1] = o[j][1] * ib;
        hout[base1]     = o[j][2] * ia;
        hout[base1 + 1] = o[j][3] * ib;
    }
}

// ---------------------------------------------------------------------------
// Launch
// ---------------------------------------------------------------------------
extern "C" void kernel_launch(void* const* d_in, const int* in_sizes, int n_in,
                              void* d_out, int out_size)
{
    const float* x      = (const float*)d_in[0];
    const float* norm_w = (const float*)d_in[1];
    const float* norm_b = (const float*)d_in[2];
    const float* qkv_w  = (const float*)d_in[3];
    const float* qkv_b  = (const float*)d_in[4];
    const float* proj_w = (const float*)d_in[5];
    const float* proj_b = (const float*)d_in[6];
    float* out = (float*)d_out;

    float *normed_p, *qkv_p, *h_p;
    cudaGetSymbolAddress((void**)&normed_p, g_normed);
    cudaGetSymbolAddress((void**)&qkv_p,   g_qkv);
    cudaGetSymbolAddress((void**)&h_p,     g_h);

    // 1. GroupNorm
    groupnorm_kernel<<<B * 16, 256>>>(x, norm_w, norm_b, normed_p);

    // 2. QKV GEMM: [768,256] x [256,4096] per batch, + bias
    gemm_kernel<<<dim3(T / 64, 768 / 64, B), 256>>>(
        qkv_w, normed_p, qkv_b, nullptr, qkv_p,
        256, (size_t)C * T, (size_t)768 * T, 0);

    // 3. Flash attention (tf32 tensor-core): 16 (b,h) x 32 query tiles of 128
    const int ATTN_SMEM = (2 * 64 * PADK + BM * PADP) * 4 + 2 * BM * 4; // 70656 B
    cudaFuncSetAttribute(attn_kernel, cudaFuncAttributeMaxDynamicSharedMemorySize,
                         ATTN_SMEM);
    attn_kernel<<<dim3(T / BM, 16), 256, ATTN_SMEM>>>(qkv_p, h_p);

    // 4. Proj GEMM + bias + residual -> d_out
    gemm_kernel<<<dim3(T / 64, 256 / 64, B), 256>>>(
        proj_w, h_p, proj_b, x, out,
        256, (size_t)C * T, (size_t)C * T, (size_t)C * T);
}

// round 3
// speedup vs baseline: 6.9813x; 2.3200x over previous
#include <cuda_runtime.h>
#include <cuda_bf16.h>
#include <math.h>

#define T 4096
#define C 256
#define B 4

// Scratch (allocation-free rule: __device__ globals)
__device__ float g_normed[B * C * T];
__device__ float g_qkv[B * 3 * C * T];
__device__ float g_h[B * C * T];
__device__ float g_part[64][8][2];     // per-(b,g) partial sums

// ---------------------------------------------------------------------------
// helpers
// ---------------------------------------------------------------------------
__device__ __forceinline__ unsigned f2tf32(float f) {
    unsigned r;
    asm("cvt.rna.tf32.f32 %0, %1;" : "=r"(r) : "f"(f));
    return r;
}

__device__ __forceinline__ unsigned pack_bf16(float a, float b) {
    __nv_bfloat162 h = __floats2bfloat162_rn(a, b);
    return *reinterpret_cast<unsigned*>(&h);
}

__device__ __forceinline__ void mma_tf32(float* d, const unsigned* a,
                                         unsigned b0, unsigned b1) {
    asm volatile(
        "mma.sync.aligned.m16n8k8.row.col.f32.tf32.tf32.f32 "
        "{%0,%1,%2,%3}, {%4,%5,%6,%7}, {%8,%9}, {%0,%1,%2,%3};"
        : "+f"(d[0]), "+f"(d[1]), "+f"(d[2]), "+f"(d[3])
        : "r"(a[0]), "r"(a[1]), "r"(a[2]), "r"(a[3]), "r"(b0), "r"(b1));
}

__device__ __forceinline__ void mma_bf16(float* d, const unsigned* a,
                                         unsigned b0, unsigned b1) {
    asm volatile(
        "mma.sync.aligned.m16n8k16.row.col.f32.bf16.bf16.f32 "
        "{%0,%1,%2,%3}, {%4,%5,%6,%7}, {%8,%9}, {%0,%1,%2,%3};"
        : "+f"(d[0]), "+f"(d[1]), "+f"(d[2]), "+f"(d[3])
        : "r"(a[0]), "r"(a[1]), "r"(a[2]), "r"(a[3]), "r"(b0), "r"(b1));
}

__device__ __forceinline__ void ldsm_x2(unsigned& r0, unsigned& r1, unsigned addr) {
    asm volatile("ldmatrix.sync.aligned.m8n8.x2.shared.b16 {%0,%1}, [%2];"
                 : "=r"(r0), "=r"(r1) : "r"(addr));
}

__device__ __forceinline__ void ldsm_x2_trans(unsigned& r0, unsigned& r1, unsigned addr) {
    asm volatile("ldmatrix.sync.aligned.m8n8.x2.trans.shared.b16 {%0,%1}, [%2];"
                 : "=r"(r0), "=r"(r1) : "r"(addr));
}

// ---------------------------------------------------------------------------
// GroupNorm, two-pass. Pass 1: 512 blocks of partial sums (8 per group).
// ---------------------------------------------------------------------------
__global__ void gn_partial(const float* __restrict__ x)
{
    int blk = blockIdx.x;
    int bg = blk >> 3, ck = blk & 7;
    const float* xb = x + (size_t)bg * 65536 + ck * 8192;
    float s = 0.f, ss = 0.f;
    for (int i = threadIdx.x; i < 2048; i += 256) {
        float4 v = *(const float4*)&xb[i * 4];
        s  += v.x + v.y + v.z + v.w;
        ss += v.x * v.x + v.y * v.y + v.z * v.z + v.w * v.w;
    }
    __shared__ float rs[256], rss[256];
    rs[threadIdx.x] = s; rss[threadIdx.x] = ss;
    __syncthreads();
    for (int off = 128; off > 0; off >>= 1) {
        if (threadIdx.x < off) {
            rs[threadIdx.x]  += rs[threadIdx.x + off];
            rss[threadIdx.x] += rss[threadIdx.x + off];
        }
        __syncthreads();
    }
    if (threadIdx.x == 0) {
        g_part[bg][ck][0] = rs[0];
        g_part[bg][ck][1] = rss[0];
    }
}

// Pass 2: 1024 blocks, each normalizes one channel (4096 elems).
__global__ void gn_apply(const float* __restrict__ x,
                         const float* __restrict__ w,
                         const float* __restrict__ bias,
                         float* __restrict__ out)
{
    int blk = blockIdx.x;
    int bg = blk >> 4, ck = blk & 15;
    float s = 0.f, ss = 0.f;
    #pragma unroll
    for (int i = 0; i < 8; i++) { s += g_part[bg][i][0]; ss += g_part[bg][i][1]; }
    float mean = s * (1.f / 65536.f);
    float inv  = rsqrtf(ss * (1.f / 65536.f) - mean * mean + 1e-5f);
    int ch = (bg & 15) * 16 + ck;
    float gm = w[ch] * inv;
    float bt = bias[ch] - mean * gm;

    const float* xb = x + (size_t)bg * 65536 + ck * 4096;
    float*       ob = out + (size_t)bg * 65536 + ck * 4096;
    for (int i = threadIdx.x; i < 1024; i += 256) {
        float4 v = *(const float4*)&xb[i * 4];
        v.x = v.x * gm + bt; v.y = v.y * gm + bt;
        v.z = v.z * gm + bt; v.w = v.w * gm + bt;
        *(float4*)&ob[i * 4] = v;
    }
}

// ---------------------------------------------------------------------------
// tf32 tensor-core GEMM: out[b][o][t] = W[o][:] . X[b][:][t] + bias[o] (+res)
// Tile 128(o) x 64(t), k-step 8, 8 warps.
// ---------------------------------------------------------------------------
__global__ void __launch_bounds__(256)
gemm_mma(const float* __restrict__ W, const float* __restrict__ X,
         const float* __restrict__ bias, const float* __restrict__ res,
         float* __restrict__ out,
         int K, size_t strideX, size_t strideO, size_t strideR)
{
    __shared__ float Wt[128 * 9];
    __shared__ float Xt[8 * 72];

    int t0 = blockIdx.x * 64, o0 = blockIdx.y * 128, b = blockIdx.z;
    const float* Xb = X + (size_t)b * strideX;
    float*       Ob = out + (size_t)b * strideO;

    int tid = threadIdx.x, w = tid >> 5, lane = tid & 31;
    int qr = lane >> 2, ql = lane & 3;

    float acc[8][4] = {};

    for (int kk = 0; kk < K; kk += 8) {
        {
            int ol = tid >> 1, c4 = (tid & 1) * 4;
            float4 v = *(const float4*)&W[(size_t)(o0 + ol) * K + kk + c4];
            Wt[ol * 9 + c4 + 0] = v.x; Wt[ol * 9 + c4 + 1] = v.y;
            Wt[ol * 9 + c4 + 2] = v.z; Wt[ol * 9 + c4 + 3] = v.w;
        }
        {
            int c = tid >> 5, t2 = (tid & 31) * 2;
            float2 v = *(const float2*)&Xb[(size_t)(kk + c) * T + t0 + t2];
            *(float2*)&Xt[c * 72 + t2] = v;
        }
        __syncthreads();

        unsigned a[4];
        a[0] = f2tf32(Wt[(16 * w + qr) * 9 + ql]);
        a[1] = f2tf32(Wt[(16 * w + qr + 8) * 9 + ql]);
        a[2] = f2tf32(Wt[(16 * w + qr) * 9 + ql + 4]);
        a[3] = f2tf32(Wt[(16 * w + qr + 8) * 9 + ql + 4]);
        #pragma unroll
        for (int nt = 0; nt < 8; nt++) {
            unsigned b0 = f2tf32(Xt[ql * 72 + nt * 8 + qr]);
            unsigned b1 = f2tf32(Xt[(ql + 4) * 72 + nt * 8 + qr]);
            mma_tf32(acc[nt], a, b0, b1);
        }
        __syncthreads();
    }

    int r0 = o0 + 16 * w + qr, r1 = r0 + 8;
    float bv0 = bias[r0], bv1 = bias[r1];
    const float* Rb = res ? res + (size_t)b * strideR : nullptr;
    #pragma unroll
    for (int nt = 0; nt < 8; nt++) {
        int t = t0 + nt * 8 + 2 * ql;
        float2 v0 = make_float2(acc[nt][0] + bv0, acc[nt][1] + bv0);
        float2 v1 = make_float2(acc[nt][2] + bv1, acc[nt][3] + bv1);
        if (Rb) {
            v0.x += Rb[(size_t)r0 * T + t]; v0.y += Rb[(size_t)r0 * T + t + 1];
            v1.x += Rb[(size_t)r1 * T + t]; v1.y += Rb[(size_t)r1 * T + t + 1];
        }
        *(float2*)&Ob[(size_t)r0 * T + t] = v0;
        *(float2*)&Ob[(size_t)r1 * T + t] = v1;
    }
}

// ---------------------------------------------------------------------------
// Flash attention, bf16 m16n8k16 + ldmatrix.
// Block: 128 queries, key tiles of 64, d=64, 8 warps.
// Ks/Vs stored [c][s] (natural, conflict-free); Ps stored [t][s].
// QK B-operand: ldmatrix.x2.trans on Ks. PV B-operand: ldmatrix.x2 on Ps.
// ---------------------------------------------------------------------------
#define BM 128
#define PK 72   // row stride (bf16 elems) for Ks/Vs/Ps: 144B rows, banks 4r..4r+3

__global__ void __launch_bounds__(256, 2)
attn_kernel(const float* __restrict__ qkv, float* __restrict__ hout)
{
    __shared__ __nv_bfloat16 Ks[64 * PK];
    __shared__ __nv_bfloat16 Vs[64 * PK];
    __shared__ __nv_bfloat16 Ps[BM * PK];
    __shared__ float rsc[BM];
    __shared__ float l_s[BM];

    int t0 = blockIdx.x * BM;
    int bh = blockIdx.y;
    int b = bh >> 2, hd = bh & 3;
    const float* qp = qkv + ((size_t)b * 768 + (size_t)hd * 192) * T;
    const float* kp = qp + (size_t)64 * T;
    const float* vp = qp + (size_t)128 * T;

    int tid = threadIdx.x, w = tid >> 5, lane = tid & 31;
    int qr = lane >> 2, ql = lane & 3;

    unsigned ks_u = (unsigned)__cvta_generic_to_shared(Ks);
    unsigned ps_u = (unsigned)__cvta_generic_to_shared(Ps);
    // QK B ldmatrix lane address: row (kk*16 + lane&15), col nt*8
    unsigned kaddr_lane = ks_u + (unsigned)((lane & 15) * PK) * 2u;
    // PV B ldmatrix lane address: row (trow + lane&7), col kk*16 + (lane&8)
    unsigned paddr_lane = ps_u + (unsigned)((lane & 7) * PK + (lane & 8)) * 2u;

    // ---- Q fragments (bf16 pairs), rows t = t0+16w+qr(+8), k = channel ----
    unsigned qf[4][4];
    {
        int tq = t0 + 16 * w + qr;
        #pragma unroll
        for (int kk = 0; kk < 4; kk++) {
            int c0 = kk * 16 + 2 * ql;
            qf[kk][0] = pack_bf16(qp[(size_t)c0 * T + tq] * 0.125f,
                                  qp[(size_t)(c0 + 1) * T + tq] * 0.125f);
            qf[kk][1] = pack_bf16(qp[(size_t)c0 * T + tq + 8] * 0.125f,
                                  qp[(size_t)(c0 + 1) * T + tq + 8] * 0.125f);
            qf[kk][2] = pack_bf16(qp[(size_t)(c0 + 8) * T + tq] * 0.125f,
                                  qp[(size_t)(c0 + 9) * T + tq] * 0.125f);
            qf[kk][3] = pack_bf16(qp[(size_t)(c0 + 8) * T + tq + 8] * 0.125f,
                                  qp[(size_t)(c0 + 9) * T + tq + 8] * 0.125f);
        }
    }

    int mi = w & 3, nb = (w >> 2) * 8;
    float o[8][4] = {};
    float m0 = -1e30f, m1 = -1e30f, l0 = 0.f, l1 = 0.f;

    for (int s0 = 0; s0 < T; s0 += 64) {
        __syncthreads();
        // ---- load K,V tiles [c][s], bf16x2 packed stores ----
        #pragma unroll
        for (int idx = tid; idx < 2048; idx += 256) {
            int c = idx >> 5, s = (idx & 31) * 2;
            float2 kv = *(const float2*)&kp[(size_t)c * T + s0 + s];
            float2 vv = *(const float2*)&vp[(size_t)c * T + s0 + s];
            *(unsigned*)&Ks[c * PK + s] = pack_bf16(kv.x, kv.y);
            *(unsigned*)&Vs[c * PK + s] = pack_bf16(vv.x, vv.y);
        }
        __syncthreads();

        // ---- S = Q K : rows 16w..16w+15, cols 0..63 ----
        float sf[8][4] = {};
        #pragma unroll
        for (int kk = 0; kk < 4; kk++) {
            unsigned kbase = kaddr_lane + (unsigned)(kk * 16 * PK) * 2u;
            #pragma unroll
            for (int nt = 0; nt < 8; nt++) {
                unsigned b0, b1;
                ldsm_x2_trans(b0, b1, kbase + nt * 16u);
                mma_bf16(sf[nt], qf[kk], b0, b1);
            }
        }

        // ---- online softmax (rows r0=16w+qr, r1=r0+8) ----
        float mx0 = -1e30f, mx1 = -1e30f;
        #pragma unroll
        for (int nt = 0; nt < 8; nt++) {
            mx0 = fmaxf(mx0, fmaxf(sf[nt][0], sf[nt][1]));
            mx1 = fmaxf(mx1, fmaxf(sf[nt][2], sf[nt][3]));
        }
        mx0 = fmaxf(mx0, __shfl_xor_sync(0xffffffffu, mx0, 1));
        mx0 = fmaxf(mx0, __shfl_xor_sync(0xffffffffu, mx0, 2));
        mx1 = fmaxf(mx1, __shfl_xor_sync(0xffffffffu, mx1, 1));
        mx1 = fmaxf(mx1, __shfl_xor_sync(0xffffffffu, mx1, 2));

        float mn0 = fmaxf(m0, mx0), mn1 = fmaxf(m1, mx1);
        float r0 = __expf(m0 - mn0), r1 = __expf(m1 - mn1);
        m0 = mn0; m1 = mn1;

        float sum0 = 0.f, sum1 = 0.f;
        __nv_bfloat16* prow0 = Ps + (16 * w + qr) * PK;
        __nv_bfloat16* prow1 = prow0 + 8 * PK;
        #pragma unroll
        for (int nt = 0; nt < 8; nt++) {
            float p00 = __expf(sf[nt][0] - mn0);
            float p01 = __expf(sf[nt][1] - mn0);
            float p10 = __expf(sf[nt][2] - mn1);
            float p11 = __expf(sf[nt][3] - mn1);
            sum0 += p00 + p01;
            sum1 += p10 + p11;
            *(unsigned*)&prow0[nt * 8 + 2 * ql] = pack_bf16(p00, p01);
            *(unsigned*)&prow1[nt * 8 + 2 * ql] = pack_bf16(p10, p11);
        }
        sum0 += __shfl_xor_sync(0xffffffffu, sum0, 1);
        sum0 += __shfl_xor_sync(0xffffffffu, sum0, 2);
        sum1 += __shfl_xor_sync(0xffffffffu, sum1, 1);
        sum1 += __shfl_xor_sync(0xffffffffu, sum1, 2);
        l0 = l0 * r0 + sum0;
        l1 = l1 * r1 + sum1;
        if (ql == 0) {
            rsc[16 * w + qr]     = r0;
            rsc[16 * w + qr + 8] = r1;
        }
        __syncthreads();

        // ---- rescale accumulators by rsc[t] ----
        #pragma unroll
        for (int j = 0; j < 8; j++) {
            float ra = rsc[(nb + j) * 8 + 2 * ql];
            float rb = rsc[(nb + j) * 8 + 2 * ql + 1];
            o[j][0] *= ra; o[j][1] *= rb; o[j][2] *= ra; o[j][3] *= rb;
        }

        // ---- O[c][t] += V[c][s] * P'[s][t] ----
        #pragma unroll
        for (int kk = 0; kk < 4; kk++) {
            unsigned a[4];
            const __nv_bfloat16* vrow = Vs + (mi * 16 + qr) * PK;
            a[0] = *(const unsigned*)&vrow[kk * 16 + 2 * ql];
            a[1] = *(const unsigned*)&vrow[8 * PK + kk * 16 + 2 * ql];
            a[2] = *(const unsigned*)&vrow[kk * 16 + 2 * ql + 8];
            a[3] = *(const unsigned*)&vrow[8 * PK + kk * 16 + 2 * ql + 8];
            unsigned pbase = paddr_lane + (unsigned)(kk * 16) * 2u;
            #pragma unroll
            for (int j = 0; j < 8; j++) {
                unsigned b0, b1;
                ldsm_x2(b0, b1, pbase + (unsigned)((nb + j) * 8 * PK) * 2u);
                mma_bf16(o[j], a, b0, b1);
            }
        }
    }

    // ---- epilogue ----
    if (ql == 0) {
        l_s[16 * w + qr]     = l0;
        l_s[16 * w + qr + 8] = l1;
    }
    __syncthreads();

    #pragma unroll
    for (int j = 0; j < 8; j++) {
        int tl = (nb + j) * 8 + 2 * ql;
        float ia = 1.f / l_s[tl];
        float ib = 1.f / l_s[tl + 1];
        int t = t0 + tl;
        int c0g = hd * 64 + mi * 16 + qr;
        size_t base0 = ((size_t)b * 256 + c0g) * T + t;
        size_t base1 = ((size_t)b * 256 + c0g + 8) * T + t;
        hout[base0]     = o[j][0] * ia;
        hout[base0 + 1] = o[j][1] * ib;
        hout[base1]     = o[j][2] * ia;
        hout[base1 + 1] = o[j][3] * ib;
    }
}

// ---------------------------------------------------------------------------
// Launch
// ---------------------------------------------------------------------------
extern "C" void kernel_launch(void* const* d_in, const int* in_sizes, int n_in,
                              void* d_out, int out_size)
{
    const float* x      = (const float*)d_in[0];
    const float* norm_w = (const float*)d_in[1];
    const float* norm_b = (const float*)d_in[2];
    const float* qkv_w  = (const float*)d_in[3];
    const float* qkv_b  = (const float*)d_in[4];
    const float* proj_w = (const float*)d_in[5];
    const float* proj_b = (const float*)d_in[6];
    float* out = (float*)d_out;

    float *normed_p, *qkv_p, *h_p;
    cudaGetSymbolAddress((void**)&normed_p, g_normed);
    cudaGetSymbolAddress((void**)&qkv_p,   g_qkv);
    cudaGetSymbolAddress((void**)&h_p,     g_h);

    // 1. GroupNorm (two-pass)
    gn_partial<<<512, 256>>>(x);
    gn_apply<<<1024, 256>>>(x, norm_w, norm_b, normed_p);

    // 2. QKV GEMM (tf32 mma): [768,256] x [256,4096] per batch + bias
    gemm_mma<<<dim3(T / 64, 768 / 128, B), 256>>>(
        qkv_w, normed_p, qkv_b, nullptr, qkv_p,
        256, (size_t)C * T, (size_t)768 * T, 0);

    // 3. Flash attention (bf16 mma + ldmatrix)
    attn_kernel<<<dim3(T / BM, 16), 256>>>(qkv_p, h_p);

    // 4. Proj GEMM (tf32 mma) + bias + residual -> d_out
    gemm_mma<<<dim3(T / 64, 256 / 128, B), 256>>>(
        proj_w, h_p, proj_b, x, out,
        256, (size_t)C * T, (size_t)C * T, (size_t)C * T);
}

// round 4
// speedup vs baseline: 7.5495x; 1.0814x over previous
#include <cuda_runtime.h>
#include <cuda_bf16.h>
#include <math.h>

#define T 4096
#define C 256
#define B 4

// Scratch (allocation-free rule: __device__ globals)
__device__ float g_normed[B * C * T];
__device__ __nv_bfloat16 g_qkv[B * 3 * C * T];   // bf16, q pre-scaled by 0.125
__device__ float g_h[B * C * T];
__device__ float g_part[64][8][2];

// ---------------------------------------------------------------------------
// helpers
// ---------------------------------------------------------------------------
__device__ __forceinline__ unsigned f2tf32(float f) {
    unsigned r;
    asm("cvt.rna.tf32.f32 %0, %1;" : "=r"(r) : "f"(f));
    return r;
}
__device__ __forceinline__ unsigned pack_bf16(float a, float b) {
    __nv_bfloat162 h = __floats2bfloat162_rn(a, b);
    return *reinterpret_cast<unsigned*>(&h);
}
__device__ __forceinline__ void mma_tf32(float* d, const unsigned* a,
                                         unsigned b0, unsigned b1) {
    asm volatile(
        "mma.sync.aligned.m16n8k8.row.col.f32.tf32.tf32.f32 "
        "{%0,%1,%2,%3}, {%4,%5,%6,%7}, {%8,%9}, {%0,%1,%2,%3};"
        : "+f"(d[0]), "+f"(d[1]), "+f"(d[2]), "+f"(d[3])
        : "r"(a[0]), "r"(a[1]), "r"(a[2]), "r"(a[3]), "r"(b0), "r"(b1));
}
__device__ __forceinline__ void mma_bf16(float* d, const unsigned* a,
                                         unsigned b0, unsigned b1) {
    asm volatile(
        "mma.sync.aligned.m16n8k16.row.col.f32.bf16.bf16.f32 "
        "{%0,%1,%2,%3}, {%4,%5,%6,%7}, {%8,%9}, {%0,%1,%2,%3};"
        : "+f"(d[0]), "+f"(d[1]), "+f"(d[2]), "+f"(d[3])
        : "r"(a[0]), "r"(a[1]), "r"(a[2]), "r"(a[3]), "r"(b0), "r"(b1));
}
__device__ __forceinline__ void ldsm_x4(unsigned& r0, unsigned& r1,
                                        unsigned& r2, unsigned& r3, unsigned addr) {
    asm volatile("ldmatrix.sync.aligned.m8n8.x4.shared.b16 {%0,%1,%2,%3}, [%4];"
                 : "=r"(r0), "=r"(r1), "=r"(r2), "=r"(r3) : "r"(addr));
}
__device__ __forceinline__ void ldsm_x4_trans(unsigned& r0, unsigned& r1,
                                              unsigned& r2, unsigned& r3, unsigned addr) {
    asm volatile("ldmatrix.sync.aligned.m8n8.x4.trans.shared.b16 {%0,%1,%2,%3}, [%4];"
                 : "=r"(r0), "=r"(r1), "=r"(r2), "=r"(r3) : "r"(addr));
}
#define CP16(dst, src) \
    asm volatile("cp.async.cg.shared.global [%0], [%1], 16;" :: "r"(dst), "l"(src))

// ---------------------------------------------------------------------------
// GroupNorm, two-pass
// ---------------------------------------------------------------------------
__global__ void gn_partial(const float* __restrict__ x)
{
    int blk = blockIdx.x;
    int bg = blk >> 3, ck = blk & 7;
    const float* xb = x + (size_t)bg * 65536 + ck * 8192;
    float s = 0.f, ss = 0.f;
    for (int i = threadIdx.x; i < 2048; i += 256) {
        float4 v = *(const float4*)&xb[i * 4];
        s  += v.x + v.y + v.z + v.w;
        ss += v.x * v.x + v.y * v.y + v.z * v.z + v.w * v.w;
    }
    __shared__ float rs[256], rss[256];
    rs[threadIdx.x] = s; rss[threadIdx.x] = ss;
    __syncthreads();
    for (int off = 128; off > 0; off >>= 1) {
        if (threadIdx.x < off) {
            rs[threadIdx.x]  += rs[threadIdx.x + off];
            rss[threadIdx.x] += rss[threadIdx.x + off];
        }
        __syncthreads();
    }
    if (threadIdx.x == 0) {
        g_part[bg][ck][0] = rs[0];
        g_part[bg][ck][1] = rss[0];
    }
}

__global__ void gn_apply(const float* __restrict__ x,
                         const float* __restrict__ w,
                         const float* __restrict__ bias,
                         float* __restrict__ out)
{
    int blk = blockIdx.x;
    int bg = blk >> 4, ck = blk & 15;
    float s = 0.f, ss = 0.f;
    #pragma unroll
    for (int i = 0; i < 8; i++) { s += g_part[bg][i][0]; ss += g_part[bg][i][1]; }
    float mean = s * (1.f / 65536.f);
    float inv  = rsqrtf(ss * (1.f / 65536.f) - mean * mean + 1e-5f);
    int ch = (bg & 15) * 16 + ck;
    float gm = w[ch] * inv;
    float bt = bias[ch] - mean * gm;

    const float* xb = x + (size_t)bg * 65536 + ck * 4096;
    float*       ob = out + (size_t)bg * 65536 + ck * 4096;
    for (int i = threadIdx.x; i < 1024; i += 256) {
        float4 v = *(const float4*)&xb[i * 4];
        v.x = v.x * gm + bt; v.y = v.y * gm + bt;
        v.z = v.z * gm + bt; v.w = v.w * gm + bt;
        *(float4*)&ob[i * 4] = v;
    }
}

// ---------------------------------------------------------------------------
// tf32 tensor-core GEMM, tile 128(o) x 64(t), k-step 16, 8 warps.
// bf16_out=1: write bf16, scale Q rows (o%192<64) by 0.125 (for attention).
// bf16_out=0: write fp32 (+ optional residual).
// ---------------------------------------------------------------------------
__global__ void __launch_bounds__(256)
gemm_mma(const float* __restrict__ W, const float* __restrict__ X,
         const float* __restrict__ bias, const float* __restrict__ res,
         void* __restrict__ out,
         int K, size_t strideX, size_t strideO, size_t strideR, int bf16_out)
{
    __shared__ unsigned Wt[128 * 17];
    __shared__ unsigned Xt[16 * 72];

    int t0 = blockIdx.x * 64, o0 = blockIdx.y * 128, b = blockIdx.z;
    const float* Xb = X + (size_t)b * strideX;

    int tid = threadIdx.x, w = tid >> 5, lane = tid & 31;
    int qr = lane >> 2, ql = lane & 3;

    float acc[8][4] = {};

    for (int kk = 0; kk < K; kk += 16) {
        {
            int ol = tid >> 1, p8 = (tid & 1) * 8;
            const float* wp = &W[(size_t)(o0 + ol) * K + kk + p8];
            float4 v0 = *(const float4*)wp;
            float4 v1 = *(const float4*)(wp + 4);
            unsigned* d = &Wt[ol * 17 + p8];
            d[0] = f2tf32(v0.x); d[1] = f2tf32(v0.y);
            d[2] = f2tf32(v0.z); d[3] = f2tf32(v0.w);
            d[4] = f2tf32(v1.x); d[5] = f2tf32(v1.y);
            d[6] = f2tf32(v1.z); d[7] = f2tf32(v1.w);
        }
        {
            int r = tid >> 4, c4 = (tid & 15) * 4;
            float4 v = *(const float4*)&Xb[(size_t)(kk + r) * T + t0 + c4];
            unsigned* d = &Xt[r * 72 + c4];
            d[0] = f2tf32(v.x); d[1] = f2tf32(v.y);
            d[2] = f2tf32(v.z); d[3] = f2tf32(v.w);
        }
        __syncthreads();

        #pragma unroll
        for (int k8 = 0; k8 < 2; k8++) {
            unsigned a[4];
            a[0] = Wt[(16 * w + qr) * 17 + k8 * 8 + ql];
            a[1] = Wt[(16 * w + qr + 8) * 17 + k8 * 8 + ql];
            a[2] = Wt[(16 * w + qr) * 17 + k8 * 8 + ql + 4];
            a[3] = Wt[(16 * w + qr + 8) * 17 + k8 * 8 + ql + 4];
            #pragma unroll
            for (int nt = 0; nt < 8; nt++) {
                unsigned b0 = Xt[(k8 * 8 + ql) * 72 + nt * 8 + qr];
                unsigned b1 = Xt[(k8 * 8 + ql + 4) * 72 + nt * 8 + qr];
                mma_tf32(acc[nt], a, b0, b1);
            }
        }
        __syncthreads();
    }

    int r0 = o0 + 16 * w + qr, r1 = r0 + 8;
    float bv0 = bias[r0], bv1 = bias[r1];
    if (bf16_out) {
        float s0 = ((r0 % 192) < 64) ? 0.125f : 1.0f;
        float s1 = ((r1 % 192) < 64) ? 0.125f : 1.0f;
        __nv_bfloat16* Ob = (__nv_bfloat16*)out + (size_t)b * strideO;
        #pragma unroll
        for (int nt = 0; nt < 8; nt++) {
            int t = t0 + nt * 8 + 2 * ql;
            *(unsigned*)&Ob[(size_t)r0 * T + t] =
                pack_bf16((acc[nt][0] + bv0) * s0, (acc[nt][1] + bv0) * s0);
            *(unsigned*)&Ob[(size_t)r1 * T + t] =
                pack_bf16((acc[nt][2] + bv1) * s1, (acc[nt][3] + bv1) * s1);
        }
    } else {
        float* Ob = (float*)out + (size_t)b * strideO;
        const float* Rb = res ? res + (size_t)b * strideR : nullptr;
        #pragma unroll
        for (int nt = 0; nt < 8; nt++) {
            int t = t0 + nt * 8 + 2 * ql;
            float2 v0 = make_float2(acc[nt][0] + bv0, acc[nt][1] + bv0);
            float2 v1 = make_float2(acc[nt][2] + bv1, acc[nt][3] + bv1);
            if (Rb) {
                v0.x += Rb[(size_t)r0 * T + t]; v0.y += Rb[(size_t)r0 * T + t + 1];
                v1.x += Rb[(size_t)r1 * T + t]; v1.y += Rb[(size_t)r1 * T + t + 1];
            }
            *(float2*)&Ob[(size_t)r0 * T + t] = v0;
            *(float2*)&Ob[(size_t)r1 * T + t] = v1;
        }
    }
}

// ---------------------------------------------------------------------------
// Flash attention, bf16, register-resident P, cp.async double-buffered K/V.
// Block: 128 queries, 8 warps; warp owns 16 query rows, all 64 channels.
// QK: S[t][s] = Q K (A=Q regs, B=Ks[c][s] via ldsm.x4.trans)
// PV: O[t][c] = P V (A=P regs from softmax, B=Vs[c][s] via ldsm.x4)
// ---------------------------------------------------------------------------
#define BM 128
#define PK 72   // bf16 row stride: 144 B

__global__ void __launch_bounds__(256, 2)
attn_kernel(const __nv_bfloat16* __restrict__ qkv, float* __restrict__ hout)
{
    __shared__ __nv_bfloat16 Ks[2][64 * PK];
    __shared__ __nv_bfloat16 Vs[2][64 * PK];

    int t0 = blockIdx.x * BM;
    int bh = blockIdx.y;
    int b = bh >> 2, hd = bh & 3;
    const __nv_bfloat16* qp = qkv + ((size_t)b * 768 + (size_t)hd * 192) * T;
    const __nv_bfloat16* kp = qp + (size_t)64 * T;
    const __nv_bfloat16* vp = qp + (size_t)128 * T;

    int tid = threadIdx.x, w = tid >> 5, lane = tid & 31;
    int qr = lane >> 2, ql = lane & 3;

    unsigned ksu[2], vsu[2];
    ksu[0] = (unsigned)__cvta_generic_to_shared(&Ks[0][0]);
    ksu[1] = (unsigned)__cvta_generic_to_shared(&Ks[1][0]);
    vsu[0] = (unsigned)__cvta_generic_to_shared(&Vs[0][0]);
    vsu[1] = (unsigned)__cvta_generic_to_shared(&Vs[1][0]);

    // cp.async assignment: 256 threads -> 2 matrices x 64 rows x 64B halves
    int cah   = tid >> 7;             // 0=K, 1=V
    int car   = (tid & 127) >> 1;     // row 0..63
    int cao   = (tid & 1) * 64;       // byte offset in 128B row
    const __nv_bfloat16* casrc = (cah ? vp : kp) + (size_t)car * T;

    // ---- Q fragments (bf16 pairs along channel) ----
    unsigned qf[4][4];
    {
        int tq = t0 + 16 * w + qr;
        #pragma unroll
        for (int kk = 0; kk < 4; kk++) {
            int c0 = kk * 16 + 2 * ql;
            #pragma unroll
            for (int h = 0; h < 2; h++) {           // row halves qr, qr+8
                unsigned short u0 = *(const unsigned short*)&qp[(size_t)c0 * T + tq + 8 * h];
                unsigned short u1 = *(const unsigned short*)&qp[(size_t)(c0 + 1) * T + tq + 8 * h];
                qf[kk][h] = (unsigned)u0 | ((unsigned)u1 << 16);
                unsigned short u2 = *(const unsigned short*)&qp[(size_t)(c0 + 8) * T + tq + 8 * h];
                unsigned short u3 = *(const unsigned short*)&qp[(size_t)(c0 + 9) * T + tq + 8 * h];
                qf[kk][h + 2] = (unsigned)u2 | ((unsigned)u3 << 16);
            }
        }
    }

    float o[8][4] = {};
    float m0 = -1e30f, m1 = -1e30f, l0 = 0.f, l1 = 0.f;

    // prologue: stage 0
    {
        unsigned dst = (cah ? vsu[0] : ksu[0]) + car * 144 + cao;
        const char* src = (const char*)casrc + cao;
        CP16(dst, src); CP16(dst + 16, src + 16);
        CP16(dst + 32, src + 32); CP16(dst + 48, src + 48);
        asm volatile("cp.async.commit_group;");
    }

    const int NT = T / 64;
    for (int it = 0; it < NT; it++) {
        int st = it & 1;
        __syncthreads();   // buf st^1 free (everyone done computing tile it-1)
        if (it + 1 < NT) {
            unsigned dst = (cah ? vsu[st ^ 1] : ksu[st ^ 1]) + car * 144 + cao;
            const char* src = (const char*)(casrc + (size_t)(it + 1) * 64) + cao;
            CP16(dst, src); CP16(dst + 16, src + 16);
            CP16(dst + 32, src + 32); CP16(dst + 48, src + 48);
            asm volatile("cp.async.commit_group;");
            asm volatile("cp.async.wait_group 1;" ::: "memory");
        } else {
            asm volatile("cp.async.wait_group 0;" ::: "memory");
        }
        __syncthreads();

        // ---- QK: S = Q K, rows 16w..16w+15, cols 0..63 ----
        float sf[8][4] = {};
        #pragma unroll
        for (int kk = 0; kk < 4; kk++) {
            unsigned base = ksu[st] + (unsigned)((16 * kk + (lane & 15)) * 144)
                          + (unsigned)((lane >> 4) * 16);
            #pragma unroll
            for (int np = 0; np < 4; np++) {
                unsigned r0, r1, r2, r3;
                ldsm_x4_trans(r0, r1, r2, r3, base + np * 32);
                mma_bf16(sf[2 * np],     qf[kk], r0, r1);
                mma_bf16(sf[2 * np + 1], qf[kk], r2, r3);
            }
        }

        // ---- online softmax (rows r=16w+qr, r+8) ----
        float mx0 = -1e30f, mx1 = -1e30f;
        #pragma unroll
        for (int nt = 0; nt < 8; nt++) {
            mx0 = fmaxf(mx0, fmaxf(sf[nt][0], sf[nt][1]));
            mx1 = fmaxf(mx1, fmaxf(sf[nt][2], sf[nt][3]));
        }
        mx0 = fmaxf(mx0, __shfl_xor_sync(0xffffffffu, mx0, 1));
        mx0 = fmaxf(mx0, __shfl_xor_sync(0xffffffffu, mx0, 2));
        mx1 = fmaxf(mx1, __shfl_xor_sync(0xffffffffu, mx1, 1));
        mx1 = fmaxf(mx1, __shfl_xor_sync(0xffffffffu, mx1, 2));

        float mn0 = fmaxf(m0, mx0), mn1 = fmaxf(m1, mx1);
        float rr0 = __expf(m0 - mn0), rr1 = __expf(m1 - mn1);
        m0 = mn0; m1 = mn1;

        float sum0 = 0.f, sum1 = 0.f;
        unsigned pa[4][4];
        #pragma unroll
        for (int nt = 0; nt < 8; nt++) {
            float p0 = __expf(sf[nt][0] - mn0);
            float p1 = __expf(sf[nt][1] - mn0);
            float p2 = __expf(sf[nt][2] - mn1);
            float p3 = __expf(sf[nt][3] - mn1);
            sum0 += p0 + p1; sum1 += p2 + p3;
            int kk = nt >> 1, hi = (nt & 1) * 2;
            pa[kk][hi]     = pack_bf16(p0, p1);
            pa[kk][hi + 1] = pack_bf16(p2, p3);
        }
        sum0 += __shfl_xor_sync(0xffffffffu, sum0, 1);
        sum0 += __shfl_xor_sync(0xffffffffu, sum0, 2);
        sum1 += __shfl_xor_sync(0xffffffffu, sum1, 1);
        sum1 += __shfl_xor_sync(0xffffffffu, sum1, 2);
        l0 = l0 * rr0 + sum0;
        l1 = l1 * rr1 + sum1;

        // ---- rescale O (rows = this thread's softmax rows) ----
        #pragma unroll
        for (int j = 0; j < 8; j++) {
            o[j][0] *= rr0; o[j][1] *= rr0;
            o[j][2] *= rr1; o[j][3] *= rr1;
        }

        // ---- PV: O[t][c] += P[t][s] V[s][c], B via ldsm.x4 on Vs[c][s] ----
        #pragma unroll
        for (int kk = 0; kk < 4; kk++) {
            #pragma unroll
            for (int cp2 = 0; cp2 < 4; cp2++) {
                int crow = cp2 * 16 + ((lane >> 4) << 3) + (lane & 7);
                unsigned addr = vsu[st] + (unsigned)(crow * 144)
                              + (unsigned)(kk * 32 + ((lane >> 3) & 1) * 16);
                unsigned r0, r1, r2, r3;
                ldsm_x4(r0, r1, r2, r3, addr);
                mma_bf16(o[2 * cp2],     pa[kk], r0, r1);
                mma_bf16(o[2 * cp2 + 1], pa[kk], r2, r3);
            }
        }
    }

    // ---- epilogue: divide by l, write h[b][hd*64+c][t] (register-local) ----
    float i0 = 1.f / l0, i1 = 1.f / l1;
    int tq = t0 + 16 * w + qr;
    #pragma unroll
    for (int j = 0; j < 8; j++) {
        int c = hd * 64 + j * 8 + 2 * ql;
        size_t b0i = ((size_t)b * 256 + c) * T;
        hout[b0i + tq]         = o[j][0] * i0;
        hout[b0i + T + tq]     = o[j][1] * i0;
        hout[b0i + tq + 8]     = o[j][2] * i1;
        hout[b0i + T + tq + 8] = o[j][3] * i1;
    }
}

// ---------------------------------------------------------------------------
// Launch
// ---------------------------------------------------------------------------
extern "C" void kernel_launch(void* const* d_in, const int* in_sizes, int n_in,
                              void* d_out, int out_size)
{
    const float* x      = (const float*)d_in[0];
    const float* norm_w = (const float*)d_in[1];
    const float* norm_b = (const float*)d_in[2];
    const float* qkv_w  = (const float*)d_in[3];
    const float* qkv_b  = (const float*)d_in[4];
    const float* proj_w = (const float*)d_in[5];
    const float* proj_b = (const float*)d_in[6];
    float* out = (float*)d_out;

    float *normed_p, *h_p;
    __nv_bfloat16* qkv_p;
    cudaGetSymbolAddress((void**)&normed_p, g_normed);
    cudaGetSymbolAddress((void**)&qkv_p,   g_qkv);
    cudaGetSymbolAddress((void**)&h_p,     g_h);

    // 1. GroupNorm (two-pass)
    gn_partial<<<512, 256>>>(x);
    gn_apply<<<1024, 256>>>(x, norm_w, norm_b, normed_p);

    // 2. QKV GEMM (tf32) -> bf16 out, Q rows pre-scaled by 0.125
    gemm_mma<<<dim3(T / 64, 768 / 128, B), 256>>>(
        qkv_w, normed_p, qkv_b, nullptr, qkv_p,
        256, (size_t)C * T, (size_t)768 * T, 0, 1);

    // 3. Flash attention (bf16 mma, register P, cp.async pipeline)
    attn_kernel<<<dim3(T / BM, 16), 256>>>(qkv_p, h_p);

    // 4. Proj GEMM (tf32) + bias + residual -> d_out (fp32)
    gemm_mma<<<dim3(T / 64, 256 / 128, B), 256>>>(
        proj_w, h_p, proj_b, x, out,
        256, (size_t)C * T, (size_t)C * T, (size_t)C * T, 0);
}